// round 3
// baseline (speedup 1.0000x reference)
#include <cuda_runtime.h>
#include <math.h>

#define B_ 64
#define S_ 512
#define I_ 512
#define H_ 1024

// ---------------- static device scratch (no cudaMalloc allowed) ----------------
__device__ float g_xT[(size_t)S_ * I_ * B_];          // x transposed: [s][i][b]   (64 MB)
__device__ float g_h0seq[(size_t)S_ * H_ * B_];       // layer0 h sequence [s][j][b] (128 MB)
__device__ float g_Wcat0[(size_t)H_ * (I_ + H_) * 4]; // interleaved [j][k][gate i,f,o,g] (24 MB)
__device__ float g_Wcat1[(size_t)H_ * (H_ + H_) * 4]; // (32 MB)
__device__ float4 g_bias0[H_];
__device__ float4 g_bias1[H_];
__device__ float g_hbuf0[2 * H_ * B_];                // double-buffered h state [2][j][b]
__device__ float g_hbuf1[2 * H_ * B_];
__device__ unsigned g_barcnt[2];
__device__ unsigned g_bargen[2];

typedef unsigned long long ull;

__device__ __forceinline__ ull pk2(float x, float y) {
    ull r; asm("mov.b64 %0, {%1,%2};" : "=l"(r) : "f"(x), "f"(y)); return r;
}
__device__ __forceinline__ ull dup2(float x) {
    ull r; asm("mov.b64 %0, {%1,%1};" : "=l"(r) : "f"(x)); return r;
}
__device__ __forceinline__ void unpk2(ull v, float& x, float& y) {
    asm("mov.b64 {%0,%1}, %2;" : "=f"(x), "=f"(y) : "l"(v));
}
// packed 2xFP32 FMA (FFMA2) — doubles fp32 throughput vs scalar FFMA
__device__ __forceinline__ void fma2(ull& acc, ull a, ull b) {
    asm("fma.rn.f32x2 %0, %1, %2, %0;" : "+l"(acc) : "l"(a), "l"(b));
}

__device__ __forceinline__ float sig_(float x) { return 1.f / (1.f + expf(-x)); }

// ---------------- prep kernels ----------------

// g_xT[s][i][b] = x[b][s][i]
__global__ void k_transpose_x(const float* __restrict__ x) {
    size_t idx = (size_t)blockIdx.x * blockDim.x + threadIdx.x;
    int b = (int)(idx & (B_ - 1));
    size_t r = idx >> 6;
    int i = (int)(r % I_);
    int s = (int)(r / I_);
    g_xT[idx] = x[((size_t)b * S_ + s) * I_ + i];
}

// Wcat[j][k][g] : k < Kx -> Wx[g*H+j][k], else Wh[g*H+j][k-Kx]. bias4[j] = bx+bh per gate.
__global__ void k_pack_w(const float* __restrict__ Wx, const float* __restrict__ Wh,
                         const float* __restrict__ bx, const float* __restrict__ bh,
                         int layer) {
    const int Kx = layer ? H_ : I_;
    const int Kt = Kx + H_;
    float* Wcat = layer ? g_Wcat1 : g_Wcat0;
    size_t idx = (size_t)blockIdx.x * blockDim.x + threadIdx.x;
    if (idx >= (size_t)H_ * Kt) return;
    int kk = (int)(idx % Kt);
    int j  = (int)(idx / Kt);
    float4 w;
    if (kk < Kx) {
        w.x = Wx[(size_t)(0 * H_ + j) * Kx + kk];
        w.y = Wx[(size_t)(1 * H_ + j) * Kx + kk];
        w.z = Wx[(size_t)(2 * H_ + j) * Kx + kk];
        w.w = Wx[(size_t)(3 * H_ + j) * Kx + kk];
    } else {
        int k = kk - Kx;
        w.x = Wh[(size_t)(0 * H_ + j) * H_ + k];
        w.y = Wh[(size_t)(1 * H_ + j) * H_ + k];
        w.z = Wh[(size_t)(2 * H_ + j) * H_ + k];
        w.w = Wh[(size_t)(3 * H_ + j) * H_ + k];
    }
    ((float4*)Wcat)[idx] = w;
    if (kk == 0) {
        float4 bb;
        bb.x = bx[j]          + bh[j];
        bb.y = bx[H_ + j]     + bh[H_ + j];
        bb.z = bx[2 * H_ + j] + bh[2 * H_ + j];
        bb.w = bx[3 * H_ + j] + bh[3 * H_ + j];
        (layer ? g_bias1 : g_bias0)[j] = bb;
    }
}

__global__ void k_zero() {
    int idx = blockIdx.x * blockDim.x + threadIdx.x;
    if (idx < H_ * B_) { g_hbuf0[idx] = 0.f; g_hbuf1[idx] = 0.f; }
    if (idx < 2) { g_barcnt[idx] = 0u; g_bargen[idx] = 0u; }
}

// ---------------- persistent scan kernel (one layer, all 512 steps) ----------------
// grid = 128 blocks (<=148 SMs -> all co-resident), 256 threads = 8 warps.
// warp owns one hidden index j = blockIdx.x*8 + warp; lane owns batches (2*lane, 2*lane+1).
// c lives in registers; h double-buffered in gmem, grid barrier between steps.
__global__ void __launch_bounds__(256, 1)
k_lstm_scan(int layer, float* __restrict__ outB,
            float* __restrict__ hn, float* __restrict__ cn) {
    const int warp = threadIdx.x >> 5;
    const int lane = threadIdx.x & 31;
    const int j  = blockIdx.x * 8 + warp;
    const int b0 = lane * 2;
    const int Kx = layer ? H_ : I_;
    const int Kt = Kx + H_;
    const float* xsrc = layer ? g_h0seq : g_xT;
    const float* Wcat = layer ? g_Wcat1 : g_Wcat0;
    const float4 bj = (layer ? g_bias1 : g_bias0)[j];
    float* hbuf = layer ? g_hbuf1 : g_hbuf0;
    float* seqT = layer ? (float*)0 : g_h0seq;
    unsigned* cnt = &g_barcnt[layer];
    volatile unsigned* gen = &g_bargen[layer];

    const ull biasIF = pk2(bj.x, bj.y);
    const ull biasOG = pk2(bj.z, bj.w);
    const ulonglong2* __restrict__ wp = (const ulonglong2*)(Wcat + (size_t)j * Kt * 4);

    float c0 = 0.f, c1 = 0.f, hv0 = 0.f, hv1 = 0.f;

    for (int t = 0; t < S_; ++t) {
        const float* hp  = hbuf + (size_t)(t & 1) * (H_ * B_) + b0;
        float* hnx       = hbuf + (size_t)((t + 1) & 1) * (H_ * B_);
        ull aif0 = biasIF, aog0 = biasOG, aif1 = biasIF, aog1 = biasOG;

        // x-part: gates += xin_t @ Wx^T  (xin in [k][b] layout -> coalesced float2)
        const float* xr = xsrc + (size_t)t * Kx * B_ + b0;
        #pragma unroll 4
        for (int k = 0; k < Kx; ++k) {
            float2 v = __ldg((const float2*)(xr + (size_t)k * B_));
            ulonglong2 w = __ldg(wp + k);          // (wi,wf) , (wo,wg) pre-paired
            ull d0 = dup2(v.x), d1 = dup2(v.y);
            fma2(aif0, w.x, d0); fma2(aog0, w.y, d0);
            fma2(aif1, w.x, d1); fma2(aog1, w.y, d1);
        }
        // h-part: gates += h_{t-1} @ Wh^T  (.cg loads: L1 stale across steps within launch)
        const ulonglong2* wph = wp + Kx;
        #pragma unroll 4
        for (int k = 0; k < H_; ++k) {
            float2 v = __ldcg((const float2*)(hp + (size_t)k * B_));
            ulonglong2 w = __ldg(wph + k);
            ull d0 = dup2(v.x), d1 = dup2(v.y);
            fma2(aif0, w.x, d0); fma2(aog0, w.y, d0);
            fma2(aif1, w.x, d1); fma2(aog1, w.y, d1);
        }

        float gi0, gf0, go0, gg0, gi1, gf1, go1, gg1;
        unpk2(aif0, gi0, gf0); unpk2(aog0, go0, gg0);
        unpk2(aif1, gi1, gf1); unpk2(aog1, go1, gg1);

        c0  = sig_(gf0) * c0 + sig_(gi0) * tanhf(gg0);
        hv0 = sig_(go0) * tanhf(c0);
        c1  = sig_(gf1) * c1 + sig_(gi1) * tanhf(gg1);
        hv1 = sig_(go1) * tanhf(c1);

        __stcg((float2*)(hnx + (size_t)j * B_ + b0), make_float2(hv0, hv1));
        if (seqT)
            *(float2*)(seqT + ((size_t)t * H_ + j) * B_ + b0) = make_float2(hv0, hv1);
        if (outB) {
            outB[(size_t)b0 * S_ * H_ + (size_t)t * H_ + j]       = hv0;
            outB[(size_t)(b0 + 1) * S_ * H_ + (size_t)t * H_ + j] = hv1;
        }

        // ---- grid-wide barrier (all 128 blocks resident by construction) ----
        __syncthreads();
        if (threadIdx.x == 0) {
            unsigned g = *gen;
            __threadfence();
            if (atomicAdd(cnt, 1) == (unsigned)(gridDim.x - 1)) {
                *(volatile unsigned*)cnt = 0u;
                __threadfence();
                *gen = g + 1u;
            } else {
                while (*gen == g) { }
            }
            __threadfence();
        }
        __syncthreads();
    }

    if (hn) { hn[(size_t)b0 * H_ + j] = hv0; hn[(size_t)(b0 + 1) * H_ + j] = hv1; }
    if (cn) { cn[(size_t)b0 * H_ + j] = c0;  cn[(size_t)(b0 + 1) * H_ + j] = c1;  }
}

// ---------------- launch ----------------
extern "C" void kernel_launch(void* const* d_in, const int* in_sizes, int n_in,
                              void* d_out, int out_size) {
    const float* x   = (const float*)d_in[0];
    const float* Wx0 = (const float*)d_in[1];
    const float* Wh0 = (const float*)d_in[2];
    const float* bx0 = (const float*)d_in[3];
    const float* bh0 = (const float*)d_in[4];
    const float* Wx1 = (const float*)d_in[5];
    const float* Wh1 = (const float*)d_in[6];
    const float* bx1 = (const float*)d_in[7];
    const float* bh1 = (const float*)d_in[8];
    float* out = (float*)d_out;

    const size_t mainN = (size_t)B_ * S_ * H_;           // 33,554,432
    float* hn = 0; float* cn = 0;
    if ((size_t)out_size >= mainN + (size_t)4 * B_ * H_) {
        hn = out + mainN;                                 // h_n [L][B][H]
        cn = out + mainN + (size_t)2 * B_ * H_;           // c_n [L][B][H]
    }

    k_transpose_x<<<(S_ * I_ * B_) / 256, 256>>>(x);
    k_pack_w<<<(H_ * (I_ + H_) + 255) / 256, 256>>>(Wx0, Wh0, bx0, bh0, 0);
    k_pack_w<<<(H_ * (H_ + H_) + 255) / 256, 256>>>(Wx1, Wh1, bx1, bh1, 1);
    k_zero<<<(H_ * B_ + 255) / 256, 256>>>();

    k_lstm_scan<<<128, 256>>>(0, (float*)0, hn, cn);
    k_lstm_scan<<<128, 256>>>(1, out,
                              hn ? hn + (size_t)B_ * H_ : (float*)0,
                              cn ? cn + (size_t)B_ * H_ : (float*)0);
}

// round 4
// speedup vs baseline: 2.5847x; 2.5847x over previous
#include <cuda_runtime.h>
#include <math.h>
#include <stdint.h>

#define B_ 64
#define S_ 512
#define I_ 512
#define H_ 1024

typedef unsigned long long ull;

// ---------------- static device scratch (no cudaMalloc allowed) ----------------
__device__ float g_xT[(size_t)S_ * I_ * B_];             // x transposed [s][k][b] (64 MB)
__device__ float g_h0seq[(size_t)(S_ + 1) * H_ * B_];    // layer0 h: row t+1 = h0_t (128 MB), row 0 = 0 (bss)
__device__ float g_h1seq[(size_t)(S_ + 1) * H_ * B_];    // layer1 h (128 MB)
__device__ ull   g_gates0[(size_t)S_ * H_ * 128];        // x-part gate preacts, packed per (t,j,lane) (512 MB)
__device__ ull   g_gates1[(size_t)S_ * H_ * 128];        // (512 MB)
__device__ float g_Wx0p[(size_t)H_ * I_ * 4];            // [j][k][gate i,f,o,g]
__device__ float g_Wh0p[(size_t)H_ * H_ * 4];
__device__ float g_Wx1p[(size_t)H_ * H_ * 4];
__device__ float g_Wh1p[(size_t)H_ * H_ * 4];
__device__ float4 g_bias0[H_];
__device__ float4 g_bias1[H_];
__device__ unsigned g_barcnt[2];
__device__ unsigned g_bargen[2];

// ---------------- helpers ----------------
__device__ __forceinline__ ull pk2(float x, float y) {
    ull r; asm("mov.b64 %0, {%1,%2};" : "=l"(r) : "f"(x), "f"(y)); return r;
}
__device__ __forceinline__ ull dup2(float x) {
    ull r; asm("mov.b64 %0, {%1,%1};" : "=l"(r) : "f"(x)); return r;
}
__device__ __forceinline__ void unpk2(ull v, float& x, float& y) {
    asm("mov.b64 {%0,%1}, %2;" : "=f"(x), "=f"(y) : "l"(v));
}
// packed 2xFP32 FMA (FFMA2): 2 FMAs per instruction
__device__ __forceinline__ void fma2(ull& acc, ull a, ull b) {
    asm("fma.rn.f32x2 %0, %1, %2, %0;" : "+l"(acc) : "l"(a), "l"(b));
}
__device__ __forceinline__ ulonglong2 ldcg2(const ull* p) {
    ulonglong2 r;
    asm volatile("ld.global.cg.v2.u64 {%0,%1}, [%2];" : "=l"(r.x), "=l"(r.y) : "l"(p));
    return r;
}
__device__ __forceinline__ void stcg2(ull* p, ull a, ull b) {
    asm volatile("st.global.cg.v2.u64 [%0], {%1,%2};" :: "l"(p), "l"(a), "l"(b));
}
// cp.async 16B, .cg = bypass L1 (keeps L1 clean for weight residency)
__device__ __forceinline__ void cpa16(uint32_t dst, const float* src) {
    asm volatile("cp.async.cg.shared.global [%0], [%1], 16;" :: "r"(dst), "l"(src));
}
__device__ __forceinline__ float sig_(float x) { return 1.f / (1.f + expf(-x)); }

// ---------------- prep kernels ----------------
__global__ void k_transpose_x(const float* __restrict__ x) {
    size_t idx = (size_t)blockIdx.x * blockDim.x + threadIdx.x;
    int b = (int)(idx & (B_ - 1));
    size_t r = idx >> 6;
    int i = (int)(r % I_);
    int s = (int)(r / I_);
    g_xT[idx] = x[((size_t)b * S_ + s) * I_ + i];
}

// pack W [4H,K] -> [j][k][4 gates]; which: 0=Wx0(+bias0) 1=Wh0 2=Wx1(+bias1) 3=Wh1
__global__ void k_pack(const float* __restrict__ W, const float* __restrict__ bx,
                       const float* __restrict__ bh, int K, int which) {
    size_t idx = (size_t)blockIdx.x * blockDim.x + threadIdx.x;
    if (idx >= (size_t)H_ * K) return;
    int k = (int)(idx % K);
    int j = (int)(idx / K);
    float4 w;
    w.x = W[(size_t)(0 * H_ + j) * K + k];
    w.y = W[(size_t)(1 * H_ + j) * K + k];
    w.z = W[(size_t)(2 * H_ + j) * K + k];
    w.w = W[(size_t)(3 * H_ + j) * K + k];
    float* outp = (which == 0) ? g_Wx0p : (which == 1) ? g_Wh0p : (which == 2) ? g_Wx1p : g_Wh1p;
    ((float4*)outp)[idx] = w;
    if (k == 0 && (which == 0 || which == 2)) {
        float4 bb;
        bb.x = bx[j]          + bh[j];
        bb.y = bx[H_ + j]     + bh[H_ + j];
        bb.z = bx[2 * H_ + j] + bh[2 * H_ + j];
        bb.w = bx[3 * H_ + j] + bh[3 * H_ + j];
        ((which == 0) ? g_bias0 : g_bias1)[j] = bb;
    }
}

// ---------------- x-projection GEMM (time-parallel, fp-pipe bound) ----------------
// grid (S/4, H/8), 256 thr. Warp owns j, 4 timesteps; lane owns batches (2l, 2l+1).
__global__ void __launch_bounds__(256) k_gemm(int layer) {
    const int warp = threadIdx.x >> 5, lane = threadIdx.x & 31;
    const int j  = blockIdx.y * 8 + warp;
    const int b0 = lane * 2;
    const int t0 = blockIdx.x * 4;
    const int Kx = layer ? H_ : I_;
    const int ro = layer ? 1 : 0;                       // h0seq row t+1 holds h0_t
    const float* xsrc = layer ? g_h0seq : g_xT;
    const float* wpack = layer ? g_Wx1p : g_Wx0p;
    ull* gout = layer ? g_gates1 : g_gates0;
    const float4 bb = (layer ? g_bias1 : g_bias0)[j];

    const ulonglong2* __restrict__ wj = (const ulonglong2*)wpack + (size_t)j * Kx;
    const ull bIF = pk2(bb.x, bb.y), bOG = pk2(bb.z, bb.w);
    ull aIF0[4], aOG0[4], aIF1[4], aOG1[4];
    #pragma unroll
    for (int i = 0; i < 4; i++) { aIF0[i] = bIF; aOG0[i] = bOG; aIF1[i] = bIF; aOG1[i] = bOG; }

    const size_t tstride = (size_t)Kx * B_;
    const float* xb = xsrc + (size_t)(t0 + ro) * tstride + b0;
    #pragma unroll 2
    for (int k = 0; k < Kx; k++) {
        ulonglong2 w = __ldg(wj + k);
        #pragma unroll
        for (int i = 0; i < 4; i++) {
            float2 v = __ldg((const float2*)(xb + (size_t)i * tstride + (size_t)k * B_));
            ull d0 = dup2(v.x), d1 = dup2(v.y);
            fma2(aIF0[i], w.x, d0); fma2(aOG0[i], w.y, d0);
            fma2(aIF1[i], w.x, d1); fma2(aOG1[i], w.y, d1);
        }
    }
    #pragma unroll
    for (int i = 0; i < 4; i++) {
        ull* gp = gout + ((size_t)(t0 + i) * H_ + j) * 128 + lane * 4;
        stcg2(gp, aIF0[i], aOG0[i]);
        stcg2(gp + 2, aIF1[i], aOG1[i]);
    }
}

// ---------------- persistent recurrent scan ----------------
// 128 blocks (co-resident), 256 thr. Warp owns j; lane owns 2 batches; c in regs.
// h staged SMEM via double-buffered cp.async.cg (4 x 64KB chunks); Wh lives in L1.
__global__ void __launch_bounds__(256, 1)
k_scan(int layer, float* __restrict__ outB, float* __restrict__ hn, float* __restrict__ cn) {
    extern __shared__ float sm[];                       // 2 x 16384 floats = 128 KB
    const int warp = threadIdx.x >> 5, lane = threadIdx.x & 31;
    const int j  = blockIdx.x * 8 + warp;
    const int b0 = lane * 2;
    const ulonglong2* __restrict__ wj = (const ulonglong2*)(layer ? g_Wh1p : g_Wh0p) + (size_t)j * H_;
    const ull* __restrict__ gbuf = layer ? g_gates1 : g_gates0;
    float* hseq = layer ? g_h1seq : g_h0seq;
    unsigned* cnt = &g_barcnt[layer];
    volatile unsigned* gen = &g_bargen[layer];
    const uint32_t sb0 = (uint32_t)__cvta_generic_to_shared(sm);

    float c0 = 0.f, c1 = 0.f, hv0 = 0.f, hv1 = 0.f;

    for (int t = 0; t < S_; ++t) {
        // x-part gate preacts (DRAM): issue first to hide latency
        const ull* gp = gbuf + ((size_t)t * H_ + j) * 128 + lane * 4;
        ulonglong2 ga = ldcg2(gp);
        ulonglong2 gb = ldcg2(gp + 2);
        const float* hrow = hseq + (size_t)t * (H_ * B_);

        // prefetch chunk 0
        {
            #pragma unroll
            for (int n = 0; n < 16; n++) {
                int u = n * 256 + threadIdx.x;
                cpa16(sb0 + u * 16, hrow + (size_t)u * 4);
            }
            asm volatile("cp.async.commit_group;");
        }

        ull aif0 = ga.x, aog0 = ga.y, aif1 = gb.x, aog1 = gb.y;

        #pragma unroll
        for (int c = 0; c < 4; c++) {
            if (c < 3) {
                const float* src = hrow + (size_t)(c + 1) * 16384;
                uint32_t dst = sb0 + ((c + 1) & 1) * 65536;
                #pragma unroll
                for (int n = 0; n < 16; n++) {
                    int u = n * 256 + threadIdx.x;
                    cpa16(dst + u * 16, src + (size_t)u * 4);
                }
                asm volatile("cp.async.commit_group;");
                asm volatile("cp.async.wait_group 1;");
            } else {
                asm volatile("cp.async.wait_group 0;");
            }
            __syncthreads();
            const float* s = sm + (c & 1) * 16384 + b0;
            const ulonglong2* wc = wj + c * 256;
            #pragma unroll 8
            for (int kk = 0; kk < 256; kk++) {
                float2 v = *(const float2*)(s + kk * 64);   // LDS.64, conflict-free
                ulonglong2 w = __ldg(wc + kk);              // L1-resident from step 2 on
                ull d0 = dup2(v.x), d1 = dup2(v.y);
                fma2(aif0, w.x, d0); fma2(aog0, w.y, d0);
                fma2(aif1, w.x, d1); fma2(aog1, w.y, d1);
            }
            __syncthreads();
        }

        float gi0, gf0, go0, gg0, gi1, gf1, go1, gg1;
        unpk2(aif0, gi0, gf0); unpk2(aog0, go0, gg0);
        unpk2(aif1, gi1, gf1); unpk2(aog1, go1, gg1);
        c0  = sig_(gf0) * c0 + sig_(gi0) * tanhf(gg0);  hv0 = sig_(go0) * tanhf(c0);
        c1  = sig_(gf1) * c1 + sig_(gi1) * tanhf(gg1);  hv1 = sig_(go1) * tanhf(c1);

        __stcg((float2*)(hseq + (size_t)(t + 1) * (H_ * B_) + (size_t)j * B_ + b0),
               make_float2(hv0, hv1));
        if (outB) {
            outB[(size_t)b0 * S_ * H_ + (size_t)t * H_ + j]       = hv0;
            outB[(size_t)(b0 + 1) * S_ * H_ + (size_t)t * H_ + j] = hv1;
        }

        // ---- grid barrier (all 128 blocks resident) ----
        __threadfence();
        __syncthreads();
        if (threadIdx.x == 0) {
            unsigned g = *gen;
            if (atomicAdd(cnt, 1) == (unsigned)(gridDim.x - 1)) {
                *(volatile unsigned*)cnt = 0u;
                __threadfence();
                *gen = g + 1u;
            } else {
                while (*gen == g) { }
            }
            __threadfence();
        }
        __syncthreads();
    }

    if (hn) { hn[(size_t)b0 * H_ + j] = hv0; hn[(size_t)(b0 + 1) * H_ + j] = hv1; }
    if (cn) { cn[(size_t)b0 * H_ + j] = c0;  cn[(size_t)(b0 + 1) * H_ + j] = c1;  }
}

// ---------------- launch ----------------
extern "C" void kernel_launch(void* const* d_in, const int* in_sizes, int n_in,
                              void* d_out, int out_size) {
    const float* x   = (const float*)d_in[0];
    const float* Wx0 = (const float*)d_in[1];
    const float* Wh0 = (const float*)d_in[2];
    const float* bx0 = (const float*)d_in[3];
    const float* bh0 = (const float*)d_in[4];
    const float* Wx1 = (const float*)d_in[5];
    const float* Wh1 = (const float*)d_in[6];
    const float* bx1 = (const float*)d_in[7];
    const float* bh1 = (const float*)d_in[8];
    float* out = (float*)d_out;

    const size_t mainN = (size_t)B_ * S_ * H_;
    float* hn = 0; float* cn = 0;
    if ((size_t)out_size >= mainN + (size_t)4 * B_ * H_) {
        hn = out + mainN;                          // h_n [L][B][H]
        cn = out + mainN + (size_t)2 * B_ * H_;    // c_n [L][B][H]
    }

    cudaFuncSetAttribute(k_scan, cudaFuncAttributeMaxDynamicSharedMemorySize, 131072);

    k_transpose_x<<<(S_ * I_ * B_) / 256, 256>>>(x);
    k_pack<<<(H_ * I_ + 255) / 256, 256>>>(Wx0, bx0, bh0, I_, 0);
    k_pack<<<(H_ * H_ + 255) / 256, 256>>>(Wh0, bx0, bh0, H_, 1);
    k_pack<<<(H_ * H_ + 255) / 256, 256>>>(Wx1, bx1, bh1, H_, 2);
    k_pack<<<(H_ * H_ + 255) / 256, 256>>>(Wh1, bx1, bh1, H_, 3);

    dim3 ggrid(S_ / 4, H_ / 8);
    k_gemm<<<ggrid, 256>>>(0);                                      // gates0 = x @ Wx0^T + b
    k_scan<<<128, 256, 131072>>>(0, (float*)0, hn, cn);             // layer-0 recurrence
    k_gemm<<<ggrid, 256>>>(1);                                      // gates1 = h0seq @ Wx1^T + b
    k_scan<<<128, 256, 131072>>>(1, out,
                                 hn ? hn + (size_t)B_ * H_ : (float*)0,
                                 cn ? cn + (size_t)B_ * H_ : (float*)0);
}